// round 1
// baseline (speedup 1.0000x reference)
#include <cuda_runtime.h>

// ---------------------------------------------------------------------------
// LinearAttention fused pipeline (fp32, f32x2-packed FFMA), sm_100a
//
//  KA : qkv = W_qkv @ x  per batch  -> stores exp(q), exp(k), v
//  KB1: partial context  ctx_num[d,e] += exp(k)[d,n]*v[e,n], kden[d]+=exp(k)
//  KB2: ctx = num/kden;  M[hd,o] = sum_e w_out[o,he]*ctx[d,e]   (per b,h)
//  KC : y = M_b @ (scale*exp(q)/colsum_head) + b_out ; per-tile sum/sumsq
//  KD : GroupNorm over (C,H,W) per batch using deterministic partials
// ---------------------------------------------------------------------------

#define Bz     32
#define Cch    128
#define NHh    4
#define Ddim   32
#define HID    128
#define NN     4096
#define NSPLIT 32
#define SCALE  0.17677669529663687f   // 1/sqrt(32)

// scratch (allocation-free rule: __device__ globals)
__device__ float g_expq[(size_t)Bz*HID*NN];   // exp(q)   [b][hd][n]
__device__ float g_ek  [(size_t)Bz*HID*NN];   // exp(k)
__device__ float g_v   [(size_t)Bz*HID*NN];   // v
__device__ float g_cpart[(size_t)Bz*NHh*NSPLIT*Ddim*Ddim];
__device__ float g_kpart[(size_t)Bz*NHh*NSPLIT*Ddim];
__device__ float g_M   [(size_t)Bz*HID*HID];  // [b][hd][o]
__device__ float g_part[Bz*32*2];             // per (b, ntile): sum, sumsq

typedef unsigned long long u64;

__device__ __forceinline__ u64 pack2(float a, float b){
    u64 r; asm("mov.b64 %0, {%1, %2};" : "=l"(r) : "f"(a), "f"(b)); return r;
}
__device__ __forceinline__ u64 fma2(u64 a, u64 b, u64 c){
    u64 d; asm("fma.rn.f32x2 %0, %1, %2, %3;" : "=l"(d) : "l"(a), "l"(b), "l"(c)); return d;
}
__device__ __forceinline__ float2 unpack2(u64 a){
    float2 f; asm("mov.b64 {%0, %1}, %2;" : "=f"(f.x), "=f"(f.y) : "l"(a)); return f;
}

// ---------------------------------------------------------------- KA: QKV GEMM
__global__ void __launch_bounds__(256) ka_qkv(const float* __restrict__ x,
                                              const float* __restrict__ wqkv){
    const int b = blockIdx.z, ot = blockIdx.y, nt = blockIdx.x;
    __shared__ float Ws[32][128];   // Ws[k][o]
    __shared__ float Xs[32][128];   // Xs[k][n]
    const int tid = threadIdx.x;
    const int tx = tid & 15, ty = tid >> 4;
    const float* xb = x + (size_t)b*Cch*NN + nt*128;
    const float* wb = wqkv + (size_t)ot*128*Cch;

    u64 acc[8][4];
#pragma unroll
    for (int i=0;i<8;i++)
#pragma unroll
        for (int j=0;j<4;j++) acc[i][j] = 0ull;

    for (int kc = 0; kc < Cch; kc += 32){
#pragma unroll
        for (int q=0;q<4;q++){
            int idx = tid + q*256;
            int o  = idx >> 3, k4 = (idx & 7)*4;
            float4 wv = *(const float4*)(wb + o*Cch + kc + k4);
            Ws[k4+0][o]=wv.x; Ws[k4+1][o]=wv.y; Ws[k4+2][o]=wv.z; Ws[k4+3][o]=wv.w;
            int k  = idx >> 5, n4 = (idx & 31)*4;
            *(float4*)&Xs[k][n4] = *(const float4*)(xb + (size_t)(kc+k)*NN + n4);
        }
        __syncthreads();
#pragma unroll
        for (int k=0;k<32;k++){
            float4 w0 = *(float4*)&Ws[k][ty*8];
            float4 w1 = *(float4*)&Ws[k][ty*8+4];
            float4 x0 = *(float4*)&Xs[k][tx*8];
            float4 x1 = *(float4*)&Xs[k][tx*8+4];
            u64 xp[4];
            xp[0]=pack2(x0.x,x0.y); xp[1]=pack2(x0.z,x0.w);
            xp[2]=pack2(x1.x,x1.y); xp[3]=pack2(x1.z,x1.w);
            float wa[8] = {w0.x,w0.y,w0.z,w0.w,w1.x,w1.y,w1.z,w1.w};
#pragma unroll
            for (int i=0;i<8;i++){
                u64 wp = pack2(wa[i], wa[i]);
#pragma unroll
                for (int j=0;j<4;j++) acc[i][j] = fma2(wp, xp[j], acc[i][j]);
            }
        }
        __syncthreads();
    }

    float* dst = (ot==0) ? g_expq : (ot==1 ? g_ek : g_v);
#pragma unroll
    for (int i=0;i<8;i++){
        int o = ty*8 + i;
        float* row = dst + ((size_t)b*HID + o)*NN + nt*128 + tx*8;
#pragma unroll
        for (int j=0;j<4;j++){
            float2 v = unpack2(acc[i][j]);
            if (ot < 2){ v.x = __expf(v.x); v.y = __expf(v.y); }
            *(float2*)(row + 2*j) = v;
        }
    }
}

// ----------------------------------------------------- KB1: context partials
__global__ void __launch_bounds__(256) kb1(){
    const int sp = blockIdx.x, h = blockIdx.y, b = blockIdx.z;
    __shared__ float sE[4][32][36];   // [group][nn][d], padded for align+banks
    __shared__ float sV[4][32][36];
    const int tid = threadIdx.x;
    const int g = tid >> 6, t = tid & 63;
    const int td = t & 7, te = t >> 3;     // td: d-quad, te: e-quad
    const size_t rowbase = ((size_t)b*HID + h*Ddim)*NN;
    const int n0 = sp*512 + g*128;

    float acc[4][4]; float kd[4];
#pragma unroll
    for (int i=0;i<4;i++){ kd[i]=0.f;
#pragma unroll
        for (int j=0;j<4;j++) acc[i][j]=0.f; }

    for (int c=0;c<128;c+=32){
#pragma unroll
        for (int q=0;q<4;q++){
            int idx = t + q*64;
            int d = idx >> 3, c4 = (idx & 7)*4;
            float4 ev = *(const float4*)(g_ek + rowbase + (size_t)d*NN + n0 + c + c4);
            float4 vv = *(const float4*)(g_v  + rowbase + (size_t)d*NN + n0 + c + c4);
            sE[g][c4+0][d]=ev.x; sE[g][c4+1][d]=ev.y; sE[g][c4+2][d]=ev.z; sE[g][c4+3][d]=ev.w;
            sV[g][c4+0][d]=vv.x; sV[g][c4+1][d]=vv.y; sV[g][c4+2][d]=vv.z; sV[g][c4+3][d]=vv.w;
        }
        __syncthreads();
#pragma unroll
        for (int nn=0;nn<32;nn++){
            float4 a  = *(float4*)&sE[g][nn][td*4];
            float4 bb = *(float4*)&sV[g][nn][te*4];
            float av[4]={a.x,a.y,a.z,a.w};
            float bv[4]={bb.x,bb.y,bb.z,bb.w};
#pragma unroll
            for (int i=0;i<4;i++){
#pragma unroll
                for (int j=0;j<4;j++) acc[i][j] += av[i]*bv[j];
            }
            if (te==0){
#pragma unroll
                for (int i=0;i<4;i++) kd[i] += av[i];
            }
        }
        __syncthreads();
    }
    const size_t pb = ((size_t)(b*NHh+h))*NSPLIT + sp*4 + g;
    float* cp = g_cpart + pb*1024;
#pragma unroll
    for (int i=0;i<4;i++)
#pragma unroll
        for (int j=0;j<4;j++)
            cp[(td*4+i)*32 + te*4+j] = acc[i][j];
    if (te==0){
        float* kp = g_kpart + pb*32;
#pragma unroll
        for (int i=0;i<4;i++) kp[td*4+i] = kd[i];
    }
}

// ------------------------------------------- KB2: reduce ctx, build M[hd][o]
__global__ void __launch_bounds__(256) kb2(const float* __restrict__ wout){
    const int h = blockIdx.x, b = blockIdx.y;
    __shared__ float sctx[32][33];
    __shared__ float kds[32];
    __shared__ float sW[128][33];
    const int tid = threadIdx.x;
    const size_t pbase = ((size_t)(b*NHh+h))*NSPLIT;

    if (tid < 32){
        float s = 0.f;
        for (int si=0; si<NSPLIT; si++) s += g_kpart[(pbase+si)*32 + tid];
        kds[tid] = s;
    }
#pragma unroll
    for (int q=0;q<16;q++){
        int idx = tid + q*256;
        int o = idx >> 5, e = idx & 31;
        sW[o][e] = wout[o*HID + h*Ddim + e];
    }
    __syncthreads();
    {
        float4 s = make_float4(0.f,0.f,0.f,0.f);
        for (int si=0; si<NSPLIT; si++){
            float4 p = *(const float4*)(g_cpart + (pbase+si)*1024 + tid*4);
            s.x+=p.x; s.y+=p.y; s.z+=p.z; s.w+=p.w;
        }
        int d = tid >> 3, e0 = (tid & 7)*4;
        float inv = 1.0f / kds[d];
        sctx[d][e0+0]=s.x*inv; sctx[d][e0+1]=s.y*inv;
        sctx[d][e0+2]=s.z*inv; sctx[d][e0+3]=s.w*inv;
    }
    __syncthreads();
    {
        int o = tid & 127, dh = (tid >> 7)*16;
        float m[16];
#pragma unroll
        for (int dd=0;dd<16;dd++) m[dd]=0.f;
        for (int e=0;e<32;e++){
            float wv = sW[o][e];
#pragma unroll
            for (int dd=0;dd<16;dd++) m[dd] += wv * sctx[dh+dd][e];
        }
#pragma unroll
        for (int dd=0;dd<16;dd++)
            g_M[((size_t)b*HID + h*Ddim + dh+dd)*HID + o] = m[dd];
    }
}

// ------------------------- KC: y = M_b @ normalized(exp q) + bias ; partials
__global__ void __launch_bounds__(256) kc(const float* __restrict__ bout,
                                          float* __restrict__ out){
    const int nt = blockIdx.x, b = blockIdx.y;
    __shared__ float Ms[32][128];   // Ms[k][o]
    __shared__ float Ps[32][128];   // Ps[k][n]
    __shared__ float qsS[128];
    __shared__ float bs[128];
    __shared__ float red1[8], red2[8];
    const int tid = threadIdx.x, tx = tid & 15, ty = tid >> 4;
    if (tid < 128) bs[tid] = bout[tid];

    u64 acc[8][4];
#pragma unroll
    for (int i=0;i<8;i++)
#pragma unroll
        for (int j=0;j<4;j++) acc[i][j]=0ull;

    const float* mb = g_M    + (size_t)b*HID*HID;
    const float* pb = g_expq + (size_t)b*HID*NN + nt*128;

    for (int kc_ = 0; kc_ < HID; kc_ += 32){
#pragma unroll
        for (int q=0;q<4;q++){
            int idx = tid + q*256;
            int k = idx >> 5, n4 = (idx & 31)*4;
            *(float4*)&Ms[k][n4] = *(const float4*)(mb + (size_t)(kc_+k)*HID + n4);
            *(float4*)&Ps[k][n4] = *(const float4*)(pb + (size_t)(kc_+k)*NN  + n4);
        }
        __syncthreads();
        if (tid < 128){                      // this 32-row chunk == one head
            float s = 0.f;
#pragma unroll
            for (int k=0;k<32;k++) s += Ps[k][tid];
            qsS[tid] = SCALE / s;
        }
        __syncthreads();
#pragma unroll
        for (int q=0;q<4;q++){               // rescale Ps in place
            int idx = tid + q*256;
            int k = idx >> 5, n4 = (idx & 31)*4;
            float4 p = *(float4*)&Ps[k][n4];
            float4 qq = *(float4*)&qsS[n4];
            p.x*=qq.x; p.y*=qq.y; p.z*=qq.z; p.w*=qq.w;
            *(float4*)&Ps[k][n4] = p;
        }
        __syncthreads();
#pragma unroll
        for (int k=0;k<32;k++){
            float4 w0 = *(float4*)&Ms[k][ty*8];
            float4 w1 = *(float4*)&Ms[k][ty*8+4];
            float4 x0 = *(float4*)&Ps[k][tx*8];
            float4 x1 = *(float4*)&Ps[k][tx*8+4];
            u64 xp[4];
            xp[0]=pack2(x0.x,x0.y); xp[1]=pack2(x0.z,x0.w);
            xp[2]=pack2(x1.x,x1.y); xp[3]=pack2(x1.z,x1.w);
            float wa[8] = {w0.x,w0.y,w0.z,w0.w,w1.x,w1.y,w1.z,w1.w};
#pragma unroll
            for (int i=0;i<8;i++){
                u64 wp = pack2(wa[i], wa[i]);
#pragma unroll
                for (int j=0;j<4;j++) acc[i][j] = fma2(wp, xp[j], acc[i][j]);
            }
        }
        __syncthreads();
    }

    float s1 = 0.f, s2 = 0.f;
#pragma unroll
    for (int i=0;i<8;i++){
        int o = ty*8 + i;
        float bias = bs[o];
        float* row = out + ((size_t)b*HID + o)*NN + nt*128 + tx*8;
#pragma unroll
        for (int j=0;j<4;j++){
            float2 v = unpack2(acc[i][j]);
            v.x += bias; v.y += bias;
            s1 += v.x + v.y;
            s2 += v.x*v.x + v.y*v.y;
            *(float2*)(row + 2*j) = v;
        }
    }
    // deterministic CTA reduction
#pragma unroll
    for (int off=16; off; off >>= 1){
        s1 += __shfl_xor_sync(0xffffffffu, s1, off);
        s2 += __shfl_xor_sync(0xffffffffu, s2, off);
    }
    int lane = tid & 31, w = tid >> 5;
    if (lane == 0){ red1[w] = s1; red2[w] = s2; }
    __syncthreads();
    if (tid == 0){
        float a=0.f, c2=0.f;
#pragma unroll
        for (int ww=0; ww<8; ww++){ a += red1[ww]; c2 += red2[ww]; }
        g_part[(b*32+nt)*2 + 0] = a;
        g_part[(b*32+nt)*2 + 1] = c2;
    }
}

// ----------------------------------------------------------- KD: GroupNorm
__global__ void __launch_bounds__(256) kd(float* __restrict__ out,
                                          const float* __restrict__ gamma,
                                          const float* __restrict__ beta){
    const int cx = blockIdx.x, b = blockIdx.y;
    __shared__ float sm[2];
    const int tid = threadIdx.x;
    if (tid == 0){
        float s=0.f, s2=0.f;
#pragma unroll
        for (int i=0;i<32;i++){
            s  += g_part[(b*32+i)*2 + 0];
            s2 += g_part[(b*32+i)*2 + 1];
        }
        sm[0]=s; sm[1]=s2;
    }
    __syncthreads();
    const float invN = 1.0f / ((float)HID * (float)NN);
    float mean = sm[0]*invN;
    float var  = sm[1]*invN - mean*mean;
    float rstd = rsqrtf(var + 1e-5f);

    float* base = out + (size_t)b*HID*NN + (size_t)cx*16384;
#pragma unroll
    for (int q=0;q<16;q++){
        int fi = tid + q*256;                  // float4 index within 4096
        int c  = (cx*16384 + fi*4) >> 12;      // channel
        float a  = gamma[c]*rstd;
        float bb = beta[c] - mean*a;
        float4 v = *(float4*)(base + fi*4);
        v.x = v.x*a + bb; v.y = v.y*a + bb;
        v.z = v.z*a + bb; v.w = v.w*a + bb;
        *(float4*)(base + fi*4) = v;
    }
}

// ---------------------------------------------------------------------------
extern "C" void kernel_launch(void* const* d_in, const int* in_sizes, int n_in,
                              void* d_out, int out_size){
    (void)in_sizes; (void)n_in; (void)out_size;
    const float* x     = (const float*)d_in[0];
    const float* wqkv  = (const float*)d_in[1];
    const float* wout  = (const float*)d_in[2];
    const float* bout  = (const float*)d_in[3];
    const float* gamma = (const float*)d_in[4];
    const float* beta  = (const float*)d_in[5];
    float* out = (float*)d_out;

    ka_qkv<<<dim3(32,3,32), 256>>>(x, wqkv);
    kb1   <<<dim3(8,4,32),  256>>>();
    kb2   <<<dim3(4,32),    256>>>(wout);
    kc    <<<dim3(32,32),   256>>>(bout, out);
    kd    <<<dim3(32,32),   256>>>(out, gamma, beta);
}

// round 3
// speedup vs baseline: 1.8124x; 1.8124x over previous
#include <cuda_runtime.h>
#include <cuda_bf16.h>
#include <cstdint>

// ---------------------------------------------------------------------------
// LinearAttention via warp-level bf16 HMMA (mma.sync m16n8k16), 3-pass hi/lo
// fp32 emulation. Base sm_100 target legal (no tcgen05).
//
//  prep_w : split W_qkv -> bf16 hi/lo                        (tiny)
//  ka     : per (b, n-tile of 128):
//             stage Xt[n][c] hi/lo in smem (transpose+split of x)
//             for ot in {q,k,v}: HMMA D[o=128][n=128] = W_ot @ Xt^T (3-pass)
//               ot0 -> per-head softmax over d, *scale; p hi/lo -> g_pt [n][hd]
//               ot1 -> ek = exp(.) kept in SMEM only
//               ot2 -> v kept in SMEM only; then fused ctx partials:
//                      g_cpart[d][e] = sum_n ek[d,n] v[e,n], g_kpart[d]=sum ek
//  kb2    : reduce partials, ctx/kden, fold w_out -> M2[o][hd] bf16 hi/lo
//  kc     : HMMA out[o][n] = M2 @ p^T + bias  (3-pass); GN partial sums
//  kd     : GroupNorm finalize
// ---------------------------------------------------------------------------

#define Bz     32
#define NN     4096
#define HID    128
#define NHh    4
#define NSPLIT 32
#define SCALE  0.17677669529663687f   // 1/sqrt(32)
#define PADB   136                    // bf16 row stride (272B: LDSM conflict-free)

// ------------------------------ scratch (__device__ globals, no allocs)
__device__ __align__(16) __nv_bfloat16 g_w_hi[384*128];
__device__ __align__(16) __nv_bfloat16 g_w_lo[384*128];
__device__ __align__(16) __nv_bfloat16 g_pt_hi[(size_t)Bz*NN*HID];
__device__ __align__(16) __nv_bfloat16 g_pt_lo[(size_t)Bz*NN*HID];
__device__ float g_cpart[(size_t)Bz*NHh*NSPLIT*32*32];
__device__ float g_kpart[(size_t)Bz*NHh*NSPLIT*32];
__device__ __align__(16) __nv_bfloat16 g_m_hi[(size_t)Bz*HID*HID];
__device__ __align__(16) __nv_bfloat16 g_m_lo[(size_t)Bz*HID*HID];
__device__ float g_part[Bz*32*2];

typedef unsigned long long u64;
__device__ __forceinline__ u64 pack2(float a, float b){
    u64 r; asm("mov.b64 %0, {%1, %2};" : "=l"(r) : "f"(a), "f"(b)); return r;
}
__device__ __forceinline__ u64 fma2(u64 a, u64 b, u64 c){
    u64 d; asm("fma.rn.f32x2 %0, %1, %2, %3;" : "=l"(d) : "l"(a), "l"(b), "l"(c)); return d;
}
__device__ __forceinline__ float2 unpack2(u64 a){
    float2 f; asm("mov.b64 {%0, %1}, %2;" : "=f"(f.x), "=f"(f.y) : "l"(a)); return f;
}

__device__ __forceinline__ uint32_t smem_u32(const void* p){
    uint32_t a;
    asm("{ .reg .u64 t; cvta.to.shared.u64 t, %1; cvt.u32.u64 %0, t; }"
        : "=r"(a) : "l"(p));
    return a;
}
__device__ __forceinline__ void ldsm4(uint32_t* r, uint32_t addr){
    asm volatile("ldmatrix.sync.aligned.m8n8.x4.shared.b16 {%0,%1,%2,%3}, [%4];"
        : "=r"(r[0]), "=r"(r[1]), "=r"(r[2]), "=r"(r[3]) : "r"(addr));
}
__device__ __forceinline__ void mma_bf16(float* d, const uint32_t* a, const uint32_t* b){
    asm volatile("mma.sync.aligned.m16n8k16.row.col.f32.bf16.bf16.f32 "
        "{%0,%1,%2,%3}, {%4,%5,%6,%7}, {%8,%9}, {%0,%1,%2,%3};"
        : "+f"(d[0]), "+f"(d[1]), "+f"(d[2]), "+f"(d[3])
        : "r"(a[0]), "r"(a[1]), "r"(a[2]), "r"(a[3]), "r"(b[0]), "r"(b[1]));
}

// ------------------------------ smem layout for KA (dynamic)
#define A_H   0
#define A_L   34816
#define B_H   69632
#define B_L   104448
#define EKR   139264               // 68,608 B: p-staging (ot0) / ek fp32 (ot1+)
#define XS    207872               // 16,896 B: fp32 transpose staging
#define KA_SMEM 224768
#define KC_SMEM 139264
#define EKSTR 134                  // fp32 row stride for ek/v smem

// ------------------------------ prep: split W
__global__ void __launch_bounds__(256) prep_w(const float* __restrict__ w){
    int i = blockIdx.x*256 + threadIdx.x;
    if (i < 384*128){
        float v = w[i];
        __nv_bfloat16 h = __float2bfloat16(v);
        g_w_hi[i] = h;
        g_w_lo[i] = __float2bfloat16(v - __bfloat162float(h));
    }
}

// ------------------------------ KA
__global__ void __launch_bounds__(256) ka(const float* __restrict__ x){
    extern __shared__ char smem[];
    const int tid = threadIdx.x, wid = tid >> 5, lane = tid & 31;
    const int nt = blockIdx.x, b = blockIdx.y;
    const int wm = wid & 3, wn = wid >> 2;     // 4 M-warps x 2 N-warps
    const uint32_t sbase = smem_u32(smem);

    // ---- stage B = Xt[n][c] hi/lo from x[c][n] (4 chunks of 32 c-rows)
    {
        float* xS = (float*)(smem + XS);
        __nv_bfloat16* Bh = (__nv_bfloat16*)(smem + B_H);
        __nv_bfloat16* Bl = (__nv_bfloat16*)(smem + B_L);
        const float* xb = x + (size_t)b*HID*NN + (size_t)nt*128;
        for (int cc = 0; cc < 128; cc += 32){
#pragma unroll
            for (int q=0;q<4;q++){
                int idx = tid + q*256;            // 1024 float4
                int r = idx >> 5, c4 = (idx & 31)*4;
                *(float4*)&xS[r*132 + c4] = *(const float4*)(xb + (size_t)(cc+r)*NN + c4);
            }
            __syncthreads();
#pragma unroll
            for (int q=0;q<16;q++){
                int idx = tid + q*256;            // 4096 elems
                int n = idx >> 5, c = idx & 31;
                float v = xS[c*132 + n];
                __nv_bfloat16 h = __float2bfloat16(v);
                Bh[n*PADB + cc + c] = h;
                Bl[n*PADB + cc + c] = __float2bfloat16(v - __bfloat162float(h));
            }
            __syncthreads();
        }
    }

    const int g = lane >> 2, tq = lane & 3;

    for (int ot = 0; ot < 3; ot++){
        __syncthreads();
        // ---- stage A = W[ot] hi/lo
        {
            const uint4* wh = (const uint4*)g_w_hi + (size_t)ot*2048;
            const uint4* wl = (const uint4*)g_w_lo + (size_t)ot*2048;
            __nv_bfloat16* Ah = (__nv_bfloat16*)(smem + A_H);
            __nv_bfloat16* Al = (__nv_bfloat16*)(smem + A_L);
#pragma unroll
            for (int q=0;q<8;q++){
                int idx = tid + q*256;            // 2048 uint4
                int r = idx >> 4, c8 = (idx & 15)*8;
                *(uint4*)(Ah + r*PADB + c8) = wh[idx];
                *(uint4*)(Al + r*PADB + c8) = wl[idx];
            }
        }
        __syncthreads();

        // ---- HMMA main loop: D[128o][128n], K=128, 3-pass
        float acc[2][8][4];
#pragma unroll
        for (int i=0;i<2;i++)
#pragma unroll
            for (int j=0;j<8;j++)
#pragma unroll
                for (int r=0;r<4;r++) acc[i][j][r] = 0.f;

        for (int k = 0; k < 128; k += 16){
            uint32_t ah[2][4], al[2][4];
#pragma unroll
            for (int mt=0;mt<2;mt++){
                int row = wm*32 + mt*16 + (lane & 15);
                int kh  = k + ((lane >> 4) << 3);
                ldsm4(ah[mt], sbase + A_H + (uint32_t)(row*PADB + kh)*2);
                ldsm4(al[mt], sbase + A_L + (uint32_t)(row*PADB + kh)*2);
            }
            uint32_t bh[8][2], bl[8][2];
#pragma unroll
            for (int p=0;p<4;p++){
                int nr = wn*64 + p*16 + ((lane >> 4) << 3) + (lane & 7);
                int kh = k + (((lane >> 3) & 1) << 3);
                uint32_t r4[4];
                ldsm4(r4, sbase + B_H + (uint32_t)(nr*PADB + kh)*2);
                bh[2*p][0]=r4[0]; bh[2*p][1]=r4[1]; bh[2*p+1][0]=r4[2]; bh[2*p+1][1]=r4[3];
                ldsm4(r4, sbase + B_L + (uint32_t)(nr*PADB + kh)*2);
                bl[2*p][0]=r4[0]; bl[2*p][1]=r4[1]; bl[2*p+1][0]=r4[2]; bl[2*p+1][1]=r4[3];
            }
#pragma unroll
            for (int mt=0;mt<2;mt++)
#pragma unroll
                for (int ntl=0;ntl<8;ntl++){
                    mma_bf16(acc[mt][ntl], ah[mt], bh[ntl]);
                    mma_bf16(acc[mt][ntl], ah[mt], bl[ntl]);
                    mma_bf16(acc[mt][ntl], al[mt], bh[ntl]);
                }
        }

        // ---- epilogues
        if (ot == 0){
            // exp + per-head (32-row) column softmax * SCALE
#pragma unroll
            for (int mt=0;mt<2;mt++)
#pragma unroll
                for (int ntl=0;ntl<8;ntl++)
#pragma unroll
                    for (int r=0;r<4;r++) acc[mt][ntl][r] = __expf(acc[mt][ntl][r]);
#pragma unroll
            for (int ntl=0;ntl<8;ntl++){
                float se = acc[0][ntl][0]+acc[0][ntl][2]+acc[1][ntl][0]+acc[1][ntl][2];
                float so = acc[0][ntl][1]+acc[0][ntl][3]+acc[1][ntl][1]+acc[1][ntl][3];
#pragma unroll
                for (int m=4;m<32;m<<=1){
                    se += __shfl_xor_sync(0xffffffffu, se, m);
                    so += __shfl_xor_sync(0xffffffffu, so, m);
                }
                float fe = SCALE/se, fo = SCALE/so;
#pragma unroll
                for (int mt=0;mt<2;mt++){
                    acc[mt][ntl][0]*=fe; acc[mt][ntl][2]*=fe;
                    acc[mt][ntl][1]*=fo; acc[mt][ntl][3]*=fo;
                }
            }
            // stage p hi/lo to smem [o][n] (stride 132), then coalesced transpose-write
            unsigned short* ph = (unsigned short*)(smem + EKR);
            unsigned short* pl = ph + 128*132;
#pragma unroll
            for (int mt=0;mt<2;mt++)
#pragma unroll
                for (int ntl=0;ntl<8;ntl++)
#pragma unroll
                    for (int r=0;r<4;r++){
                        int o = wm*32 + mt*16 + g + ((r>>1)<<3);
                        int n = wn*64 + ntl*8 + tq*2 + (r&1);
                        float v = acc[mt][ntl][r];
                        __nv_bfloat16 hv = __float2bfloat16(v);
                        __nv_bfloat16 lv = __float2bfloat16(v - __bfloat162float(hv));
                        ph[o*132 + n] = __bfloat16_as_ushort(hv);
                        pl[o*132 + n] = __bfloat16_as_ushort(lv);
                    }
            __syncthreads();
            {
                const size_t gb = (size_t)b*NN + (size_t)nt*128;
                uint32_t* gh = (uint32_t*)g_pt_hi;
                uint32_t* gl = (uint32_t*)g_pt_lo;
#pragma unroll
                for (int q=0;q<32;q++){
                    int idx = tid + q*256;          // 8192
                    int n = idx >> 6, u = idx & 63;
                    uint32_t hv = (uint32_t)ph[(2*u)*132 + n] | ((uint32_t)ph[(2*u+1)*132 + n] << 16);
                    uint32_t lv = (uint32_t)pl[(2*u)*132 + n] | ((uint32_t)pl[(2*u+1)*132 + n] << 16);
                    gh[(gb + n)*64 + u] = hv;
                    gl[(gb + n)*64 + u] = lv;
                }
            }
        } else if (ot == 1){
            // ek -> smem only
            float* ekS = (float*)(smem + EKR);
#pragma unroll
            for (int mt=0;mt<2;mt++)
#pragma unroll
                for (int ntl=0;ntl<8;ntl++)
#pragma unroll
                    for (int r=0;r<4;r++){
                        int o = wm*32 + mt*16 + g + ((r>>1)<<3);
                        int n = wn*64 + ntl*8 + tq*2 + (r&1);
                        ekS[o*EKSTR + n] = __expf(acc[mt][ntl][r]);
                    }
        } else {
            // v -> smem (alias A region; all mma done after this sync)
            __syncthreads();
            float* vS = (float*)(smem + A_H);
#pragma unroll
            for (int mt=0;mt<2;mt++)
#pragma unroll
                for (int ntl=0;ntl<8;ntl++)
#pragma unroll
                    for (int r=0;r<4;r++){
                        int o = wm*32 + mt*16 + g + ((r>>1)<<3);
                        int n = wn*64 + ntl*8 + tq*2 + (r&1);
                        vS[o*EKSTR + n] = acc[mt][ntl][r];
                    }
            __syncthreads();

            // ---- fused ctx partials: warp = (head, e-half)
            const float* ekS = (const float*)(smem + EKR);
            const int h = wid >> 1, eh = wid & 1;
            const int dq = lane & 7, eq = lane >> 3;
            const float* ekp = ekS + (h*32 + dq*4)*EKSTR;
            const float* vp  = (const float*)(smem + A_H) + (h*32 + eh*16 + eq*4)*EKSTR;
            u64 c2[4][4];
            float kdv[4] = {0.f,0.f,0.f,0.f};
#pragma unroll
            for (int i=0;i<4;i++)
#pragma unroll
                for (int j=0;j<4;j++) c2[i][j] = 0ull;
            for (int n2=0;n2<64;n2++){
                float2 e2[4], v2[4];
#pragma unroll
                for (int i=0;i<4;i++) e2[i] = *(const float2*)(ekp + i*EKSTR + 2*n2);
#pragma unroll
                for (int j=0;j<4;j++) v2[j] = *(const float2*)(vp  + j*EKSTR + 2*n2);
                u64 ep[4], vv[4];
#pragma unroll
                for (int i=0;i<4;i++) ep[i] = pack2(e2[i].x, e2[i].y);
#pragma unroll
                for (int j=0;j<4;j++) vv[j] = pack2(v2[j].x, v2[j].y);
#pragma unroll
                for (int i=0;i<4;i++)
#pragma unroll
                    for (int j=0;j<4;j++) c2[i][j] = fma2(ep[i], vv[j], c2[i][j]);
                if (eq == 0 && eh == 0){
#pragma unroll
                    for (int i=0;i<4;i++) kdv[i] += e2[i].x + e2[i].y;
                }
            }
            const size_t pb = ((size_t)(b*NHh + h))*NSPLIT + nt;
            float* cp = g_cpart + pb*1024;
#pragma unroll
            for (int i=0;i<4;i++)
#pragma unroll
                for (int j=0;j<4;j++){
                    float2 t = unpack2(c2[i][j]);
                    cp[(dq*4+i)*32 + eh*16 + eq*4 + j] = t.x + t.y;
                }
            if (eq == 0 && eh == 0){
#pragma unroll
                for (int i=0;i<4;i++) g_kpart[pb*32 + dq*4 + i] = kdv[i];
            }
        }
    }
}

// ------------------------------ KB2: reduce ctx, fold w_out -> M2 bf16 hi/lo
__global__ void __launch_bounds__(256) kb2(const float* __restrict__ wout){
    const int h = blockIdx.x, b = blockIdx.y;
    __shared__ float sctx[32][33];
    __shared__ float kds[32];
    __shared__ float sW[128][33];
    const int tid = threadIdx.x;
    const size_t pbase = ((size_t)(b*NHh+h))*NSPLIT;

    if (tid < 32){
        float s = 0.f;
        for (int si=0; si<NSPLIT; si++) s += g_kpart[(pbase+si)*32 + tid];
        kds[tid] = s;
    }
#pragma unroll
    for (int q=0;q<16;q++){
        int idx = tid + q*256;
        int o = idx >> 5, e = idx & 31;
        sW[o][e] = wout[o*HID + h*32 + e];
    }
    __syncthreads();
    {
        float4 s = make_float4(0.f,0.f,0.f,0.f);
        for (int si=0; si<NSPLIT; si++){
            float4 p = *(const float4*)(g_cpart + (pbase+si)*1024 + tid*4);
            s.x+=p.x; s.y+=p.y; s.z+=p.z; s.w+=p.w;
        }
        int d = tid >> 3, e0 = (tid & 7)*4;
        float inv = 1.0f / kds[d];
        sctx[d][e0+0]=s.x*inv; sctx[d][e0+1]=s.y*inv;
        sctx[d][e0+2]=s.z*inv; sctx[d][e0+3]=s.w*inv;
    }
    __syncthreads();
    {
        int o = tid & 127, dh = (tid >> 7)*16;
        float m[16];
#pragma unroll
        for (int dd=0;dd<16;dd++) m[dd]=0.f;
        for (int e=0;e<32;e++){
            float wv = sW[o][e];
#pragma unroll
            for (int dd=0;dd<16;dd++) m[dd] += wv * sctx[dh+dd][e];
        }
#pragma unroll
        for (int dd=0;dd<16;dd++){
            __nv_bfloat16 hv = __float2bfloat16(m[dd]);
            size_t a = ((size_t)b*HID + o)*HID + h*32 + dh + dd;
            g_m_hi[a] = hv;
            g_m_lo[a] = __float2bfloat16(m[dd] - __bfloat162float(hv));
        }
    }
}

// ------------------------------ KC: HMMA out-proj + bias + GN partials
__global__ void __launch_bounds__(256) kc(const float* __restrict__ bout,
                                          float* __restrict__ out){
    extern __shared__ char smem[];
    __shared__ float red1[8], red2[8];
    const int tid = threadIdx.x, wid = tid >> 5, lane = tid & 31;
    const int nt = blockIdx.x, b = blockIdx.y;
    const int wm = wid & 3, wn = wid >> 2;
    const uint32_t sbase = smem_u32(smem);
    const int g = lane >> 2, tq = lane & 3;

    // stage A = M2 hi/lo, B = p tile hi/lo
    {
        const uint4* mh = (const uint4*)g_m_hi + (size_t)b*2048;
        const uint4* ml = (const uint4*)g_m_lo + (size_t)b*2048;
        const uint4* ph = (const uint4*)g_pt_hi + ((size_t)b*NN + (size_t)nt*128)*16;
        const uint4* pl = (const uint4*)g_pt_lo + ((size_t)b*NN + (size_t)nt*128)*16;
        __nv_bfloat16* Ah = (__nv_bfloat16*)(smem + A_H);
        __nv_bfloat16* Al = (__nv_bfloat16*)(smem + A_L);
        __nv_bfloat16* Bh = (__nv_bfloat16*)(smem + B_H);
        __nv_bfloat16* Bl = (__nv_bfloat16*)(smem + B_L);
#pragma unroll
        for (int q=0;q<8;q++){
            int idx = tid + q*256;
            int r = idx >> 4, c8 = (idx & 15)*8;
            *(uint4*)(Ah + r*PADB + c8) = mh[idx];
            *(uint4*)(Al + r*PADB + c8) = ml[idx];
            *(uint4*)(Bh + r*PADB + c8) = ph[idx];
            *(uint4*)(Bl + r*PADB + c8) = pl[idx];
        }
    }
    __syncthreads();

    float acc[2][8][4];
#pragma unroll
    for (int i=0;i<2;i++)
#pragma unroll
        for (int j=0;j<8;j++)
#pragma unroll
            for (int r=0;r<4;r++) acc[i][j][r] = 0.f;

    for (int k = 0; k < 128; k += 16){
        uint32_t ah[2][4], al[2][4];
#pragma unroll
        for (int mt=0;mt<2;mt++){
            int row = wm*32 + mt*16 + (lane & 15);
            int kh  = k + ((lane >> 4) << 3);
            ldsm4(ah[mt], sbase + A_H + (uint32_t)(row*PADB + kh)*2);
            ldsm4(al[mt], sbase + A_L + (uint32_t)(row*PADB + kh)*2);
        }
        uint32_t bh[8][2], bl[8][2];
#pragma unroll
        for (int p=0;p<4;p++){
            int nr = wn*64 + p*16 + ((lane >> 4) << 3) + (lane & 7);
            int kh = k + (((lane >> 3) & 1) << 3);
            uint32_t r4[4];
            ldsm4(r4, sbase + B_H + (uint32_t)(nr*PADB + kh)*2);
            bh[2*p][0]=r4[0]; bh[2*p][1]=r4[1]; bh[2*p+1][0]=r4[2]; bh[2*p+1][1]=r4[3];
            ldsm4(r4, sbase + B_L + (uint32_t)(nr*PADB + kh)*2);
            bl[2*p][0]=r4[0]; bl[2*p][1]=r4[1]; bl[2*p+1][0]=r4[2]; bl[2*p+1][1]=r4[3];
        }
#pragma unroll
        for (int mt=0;mt<2;mt++)
#pragma unroll
            for (int ntl=0;ntl<8;ntl++){
                mma_bf16(acc[mt][ntl], ah[mt], bh[ntl]);
                mma_bf16(acc[mt][ntl], ah[mt], bl[ntl]);
                mma_bf16(acc[mt][ntl], al[mt], bh[ntl]);
            }
    }

    // epilogue: bias, writes, GN partials
    float bias[4];
#pragma unroll
    for (int r2=0;r2<4;r2++) bias[r2] = bout[wm*32 + r2*8 + g];   // rows g+{0,8,16,24}
    float s1 = 0.f, s2 = 0.f;
#pragma unroll
    for (int mt=0;mt<2;mt++)
#pragma unroll
        for (int ntl=0;ntl<8;ntl++){
#pragma unroll
            for (int half=0; half<2; half++){
                float bv = bias[mt*2 + half];
                float v0 = acc[mt][ntl][half*2+0] + bv;
                float v1 = acc[mt][ntl][half*2+1] + bv;
                s1 += v0 + v1;
                s2 += v0*v0 + v1*v1;
                int row = wm*32 + mt*16 + half*8 + g;
                int col = nt*128 + wn*64 + ntl*8 + tq*2;
                float2 w2 = make_float2(v0, v1);
                *(float2*)(out + ((size_t)(b*HID + row))*NN + col) = w2;
            }
        }
#pragma unroll
    for (int m=1;m<32;m<<=1){
        s1 += __shfl_xor_sync(0xffffffffu, s1, m);
        s2 += __shfl_xor_sync(0xffffffffu, s2, m);
    }
    if (lane == 0){ red1[wid] = s1; red2[wid] = s2; }
    __syncthreads();
    if (tid == 0){
        float a=0.f, c2s=0.f;
#pragma unroll
        for (int w=0; w<8; w++){ a += red1[w]; c2s += red2[w]; }
        g_part[(b*32+nt)*2 + 0] = a;
        g_part[(b*32+nt)*2 + 1] = c2s;
    }
}

// ------------------------------ KD: GroupNorm finalize
__global__ void __launch_bounds__(256) kd(float* __restrict__ out,
                                          const float* __restrict__ gamma,
                                          const float* __restrict__ beta){
    const int cx = blockIdx.x, b = blockIdx.y;
    __shared__ float sm[2];
    const int tid = threadIdx.x;
    if (tid == 0){
        float s=0.f, s2=0.f;
#pragma unroll
        for (int i=0;i<32;i++){
            s  += g_part[(b*32+i)*2 + 0];
            s2 += g_part[(b*32+i)*2 + 1];
        }
        sm[0]=s; sm[1]=s2;
    }
    __syncthreads();
    const float invN = 1.0f / ((float)HID * (float)NN);
    float mean = sm[0]*invN;
    float var  = sm[1]*invN - mean*mean;
    float rstd = rsqrtf(var + 1e-5f);

    float* base = out + (size_t)b*HID*NN + (size_t)cx*16384;
#pragma unroll
    for (int q=0;q<16;q++){
        int fi = tid + q*256;
        int c  = (cx*16384 + fi*4) >> 12;
        float a  = gamma[c]*rstd;
        float bb = beta[c] - mean*a;
        float4 v = *(float4*)(base + fi*4);
        v.x = v.x*a + bb; v.y = v.y*a + bb;
        v.z = v.z*a + bb; v.w = v.w*a + bb;
        *(float4*)(base + fi*4) = v;
    }
}

// ---------------------------------------------------------------------------
extern "C" void kernel_launch(void* const* d_in, const int* in_sizes, int n_in,
                              void* d_out, int out_size){
    (void)in_sizes; (void)n_in; (void)out_size;
    const float* x     = (const float*)d_in[0];
    const float* wqkv  = (const float*)d_in[1];
    const float* wout  = (const float*)d_in[2];
    const float* bout  = (const float*)d_in[3];
    const float* gamma = (const float*)d_in[4];
    const float* beta  = (const float*)d_in[5];
    float* out = (float*)d_out;

    cudaFuncSetAttribute(ka, cudaFuncAttributeMaxDynamicSharedMemorySize, KA_SMEM);
    cudaFuncSetAttribute(kc, cudaFuncAttributeMaxDynamicSharedMemorySize, KC_SMEM);

    prep_w<<<192, 256>>>(wqkv);
    ka <<<dim3(32,32), 256, KA_SMEM>>>(x);
    kb2<<<dim3(4,32),  256>>>(wout);
    kc <<<dim3(32,32), 256, KC_SMEM>>>(bout, out);
    kd <<<dim3(32,32), 256>>>(out, gamma, beta);
}

// round 4
// speedup vs baseline: 1.9874x; 1.0966x over previous
#include <cuda_runtime.h>
#include <cuda_bf16.h>
#include <cstdint>

// ---------------------------------------------------------------------------
// LinearAttention via warp-level bf16 HMMA (mma.sync m16n8k16), 3-pass hi/lo
// fp32 emulation. Base sm_100 target legal (no tcgen05).
//   prep_w : split W_qkv -> bf16 hi/lo
//   ka     : per (b, 128-wide n-tile): x staged bf16 hi/lo [c][n] (ldsm.trans);
//            3 HMMA GEMMs (q,k,v) pass-major; epilogues: softmax-p -> g_pt,
//            ek/v smem-resident, fused ctx partials (f32x2)
//   kb2    : reduce partials, fold w_out -> M2 bf16 hi/lo
//   kc     : HMMA out-proj (n-tile 64, 2 CTAs/SM) + bias + GN partials
//   kd     : GroupNorm finalize
// ---------------------------------------------------------------------------

#define Bz     32
#define NN     4096
#define HID    128
#define NHh    4
#define NSPLIT 32
#define SCALE  0.17677669529663687f   // 1/sqrt(32)
#define PADB   136                    // bf16 row stride (272B, LDSM conflict-free)
#define EKSTR  134                    // fp32 row stride for ek/v smem

// ------------------------------ scratch (__device__ globals, no allocs)
__device__ __align__(16) __nv_bfloat16 g_w_hi[384*128];
__device__ __align__(16) __nv_bfloat16 g_w_lo[384*128];
__device__ __align__(16) __nv_bfloat16 g_pt_hi[(size_t)Bz*NN*HID];
__device__ __align__(16) __nv_bfloat16 g_pt_lo[(size_t)Bz*NN*HID];
__device__ float g_cpart[(size_t)Bz*NHh*NSPLIT*32*32];
__device__ float g_kpart[(size_t)Bz*NHh*NSPLIT*32];
__device__ __align__(16) __nv_bfloat16 g_m_hi[(size_t)Bz*HID*HID];
__device__ __align__(16) __nv_bfloat16 g_m_lo[(size_t)Bz*HID*HID];
__device__ float g_part[Bz*64*2];

typedef unsigned long long u64;
__device__ __forceinline__ u64 pack2(float a, float b){
    u64 r; asm("mov.b64 %0, {%1, %2};" : "=l"(r) : "f"(a), "f"(b)); return r;
}
__device__ __forceinline__ u64 fma2(u64 a, u64 b, u64 c){
    u64 d; asm("fma.rn.f32x2 %0, %1, %2, %3;" : "=l"(d) : "l"(a), "l"(b), "l"(c)); return d;
}
__device__ __forceinline__ float2 unpack2(u64 a){
    float2 f; asm("mov.b64 {%0, %1}, %2;" : "=f"(f.x), "=f"(f.y) : "l"(a)); return f;
}
__device__ __forceinline__ uint32_t smem_u32(const void* p){
    uint32_t a;
    asm("{ .reg .u64 t; cvta.to.shared.u64 t, %1; cvt.u32.u64 %0, t; }"
        : "=r"(a) : "l"(p));
    return a;
}
__device__ __forceinline__ void ldsm4(uint32_t* r, uint32_t addr){
    asm volatile("ldmatrix.sync.aligned.m8n8.x4.shared.b16 {%0,%1,%2,%3}, [%4];"
        : "=r"(r[0]), "=r"(r[1]), "=r"(r[2]), "=r"(r[3]) : "r"(addr));
}
__device__ __forceinline__ void ldsm4t(uint32_t* r, uint32_t addr){
    asm volatile("ldmatrix.sync.aligned.m8n8.x4.trans.shared.b16 {%0,%1,%2,%3}, [%4];"
        : "=r"(r[0]), "=r"(r[1]), "=r"(r[2]), "=r"(r[3]) : "r"(addr));
}
__device__ __forceinline__ void mma_bf16(float* d, const uint32_t* a, const uint32_t* b){
    asm volatile("mma.sync.aligned.m16n8k16.row.col.f32.bf16.bf16.f32 "
        "{%0,%1,%2,%3}, {%4,%5,%6,%7}, {%8,%9}, {%0,%1,%2,%3};"
        : "+f"(d[0]), "+f"(d[1]), "+f"(d[2]), "+f"(d[3])
        : "r"(a[0]), "r"(a[1]), "r"(a[2]), "r"(a[3]), "r"(b[0]), "r"(b[1]));
}

// ------------------------------ smem layouts
#define A_H   0
#define A_L   34816
#define B_H   69632
#define B_L   104448
#define EKR   139264               // 68,608 B: p staging (ot0) / ek fp32 (ot1+)
#define KA_SMEM 207872
// kc: A 2x34816, B(64 rows) 2x17408
#define KC_B_H 69632
#define KC_B_L 87040
#define KC_SMEM 104448

// ------------------------------ prep: split W
__global__ void __launch_bounds__(256) prep_w(const float* __restrict__ w){
    int i = blockIdx.x*256 + threadIdx.x;
    if (i < 384*128){
        float v = w[i];
        __nv_bfloat16 h = __float2bfloat16(v);
        g_w_hi[i] = h;
        g_w_lo[i] = __float2bfloat16(v - __bfloat162float(h));
    }
}

// ------------------------------ KA
__global__ void __launch_bounds__(256, 1) ka(const float* __restrict__ x){
    extern __shared__ char smem[];
    const int tid = threadIdx.x, wid = tid >> 5, lane = tid & 31;
    const int nt = blockIdx.x, b = blockIdx.y;
    const int wm = wid & 3, wn = wid >> 2;     // 4 M-warps x 2 N-warps
    const uint32_t sbase = smem_u32(smem);

    // ---- stage B = x[c][n] bf16 hi/lo (natural layout; ldsm.trans at use)
    {
        __nv_bfloat16* Bh = (__nv_bfloat16*)(smem + B_H);
        __nv_bfloat16* Bl = (__nv_bfloat16*)(smem + B_L);
        const float* xb = x + (size_t)b*HID*NN + (size_t)nt*128;
#pragma unroll
        for (int q=0;q<16;q++){
            int idx = tid + q*256;               // 4096 float4
            int c = idx >> 5, n4 = (idx & 31)*4;
            float4 v = *(const float4*)(xb + (size_t)c*NN + n4);
            __nv_bfloat16 h0 = __float2bfloat16(v.x), h1 = __float2bfloat16(v.y);
            __nv_bfloat16 h2 = __float2bfloat16(v.z), h3 = __float2bfloat16(v.w);
            __nv_bfloat162 H0; H0.x = h0; H0.y = h1;
            __nv_bfloat162 H1; H1.x = h2; H1.y = h3;
            __nv_bfloat162 L0, L1;
            L0.x = __float2bfloat16(v.x - __bfloat162float(h0));
            L0.y = __float2bfloat16(v.y - __bfloat162float(h1));
            L1.x = __float2bfloat16(v.z - __bfloat162float(h2));
            L1.y = __float2bfloat16(v.w - __bfloat162float(h3));
            *(__nv_bfloat162*)(Bh + c*PADB + n4)     = H0;
            *(__nv_bfloat162*)(Bh + c*PADB + n4 + 2) = H1;
            *(__nv_bfloat162*)(Bl + c*PADB + n4)     = L0;
            *(__nv_bfloat162*)(Bl + c*PADB + n4 + 2) = L1;
        }
    }

    const int g = lane >> 2, tq = lane & 3;

    for (int ot = 0; ot < 3; ot++){
        __syncthreads();
        // ---- stage A = W[ot] hi/lo  [o][c], non-trans ldsm
        {
            const uint4* wh = (const uint4*)g_w_hi + (size_t)ot*2048;
            const uint4* wl = (const uint4*)g_w_lo + (size_t)ot*2048;
            __nv_bfloat16* Ah = (__nv_bfloat16*)(smem + A_H);
            __nv_bfloat16* Al = (__nv_bfloat16*)(smem + A_L);
#pragma unroll
            for (int q=0;q<8;q++){
                int idx = tid + q*256;            // 2048 uint4
                int r = idx >> 4, c8 = (idx & 15)*8;
                *(uint4*)(Ah + r*PADB + c8) = wh[idx];
                *(uint4*)(Al + r*PADB + c8) = wl[idx];
            }
        }
        __syncthreads();

        // ---- HMMA main loop: D[128o][128n], K=128, pass-major 3-pass
        float acc[2][8][4];
#pragma unroll
        for (int i=0;i<2;i++)
#pragma unroll
            for (int j=0;j<8;j++)
#pragma unroll
                for (int r=0;r<4;r++) acc[i][j][r] = 0.f;

        for (int k = 0; k < 128; k += 16){
            uint32_t ah[2][4], al[2][4];
#pragma unroll
            for (int mt=0;mt<2;mt++){
                int row = wm*32 + mt*16 + (lane & 15);
                int kh  = k + ((lane >> 4) << 3);
                ldsm4(ah[mt], sbase + A_H + (uint32_t)(row*PADB + kh)*2);
                ldsm4(al[mt], sbase + A_L + (uint32_t)(row*PADB + kh)*2);
            }
            uint32_t bh[8][2], bl[8][2];
            {
                int kr = k + ((lane >> 3) & 1)*8 + (lane & 7);
#pragma unroll
                for (int p=0;p<4;p++){
                    int nc = wn*64 + p*16 + ((lane >> 4) << 3);
                    uint32_t r4[4];
                    ldsm4t(r4, sbase + B_H + (uint32_t)(kr*PADB + nc)*2);
                    bh[2*p][0]=r4[0]; bh[2*p][1]=r4[1]; bh[2*p+1][0]=r4[2]; bh[2*p+1][1]=r4[3];
                    ldsm4t(r4, sbase + B_L + (uint32_t)(kr*PADB + nc)*2);
                    bl[2*p][0]=r4[0]; bl[2*p][1]=r4[1]; bl[2*p+1][0]=r4[2]; bl[2*p+1][1]=r4[3];
                }
            }
            // pass-major: long RAW distance per accumulator
#pragma unroll
            for (int mt=0;mt<2;mt++)
#pragma unroll
                for (int ntl=0;ntl<8;ntl++) mma_bf16(acc[mt][ntl], ah[mt], bh[ntl]);
#pragma unroll
            for (int mt=0;mt<2;mt++)
#pragma unroll
                for (int ntl=0;ntl<8;ntl++) mma_bf16(acc[mt][ntl], ah[mt], bl[ntl]);
#pragma unroll
            for (int mt=0;mt<2;mt++)
#pragma unroll
                for (int ntl=0;ntl<8;ntl++) mma_bf16(acc[mt][ntl], al[mt], bh[ntl]);
        }

        // ---- epilogues
        if (ot == 0){
#pragma unroll
            for (int mt=0;mt<2;mt++)
#pragma unroll
                for (int ntl=0;ntl<8;ntl++)
#pragma unroll
                    for (int r=0;r<4;r++) acc[mt][ntl][r] = __expf(acc[mt][ntl][r]);
#pragma unroll
            for (int ntl=0;ntl<8;ntl++){
                float se = acc[0][ntl][0]+acc[0][ntl][2]+acc[1][ntl][0]+acc[1][ntl][2];
                float so = acc[0][ntl][1]+acc[0][ntl][3]+acc[1][ntl][1]+acc[1][ntl][3];
#pragma unroll
                for (int m=4;m<32;m<<=1){
                    se += __shfl_xor_sync(0xffffffffu, se, m);
                    so += __shfl_xor_sync(0xffffffffu, so, m);
                }
                float fe = SCALE/se, fo = SCALE/so;
#pragma unroll
                for (int mt=0;mt<2;mt++){
                    acc[mt][ntl][0]*=fe; acc[mt][ntl][2]*=fe;
                    acc[mt][ntl][1]*=fo; acc[mt][ntl][3]*=fo;
                }
            }
            unsigned short* ph = (unsigned short*)(smem + EKR);
            unsigned short* pl = ph + 128*132;
#pragma unroll
            for (int mt=0;mt<2;mt++)
#pragma unroll
                for (int ntl=0;ntl<8;ntl++)
#pragma unroll
                    for (int r=0;r<4;r++){
                        int o = wm*32 + mt*16 + g + ((r>>1)<<3);
                        int n = wn*64 + ntl*8 + tq*2 + (r&1);
                        float v = acc[mt][ntl][r];
                        __nv_bfloat16 hv = __float2bfloat16(v);
                        __nv_bfloat16 lv = __float2bfloat16(v - __bfloat162float(hv));
                        ph[o*132 + n] = __bfloat16_as_ushort(hv);
                        pl[o*132 + n] = __bfloat16_as_ushort(lv);
                    }
            __syncthreads();
            {
                const size_t gb = (size_t)b*NN + (size_t)nt*128;
                uint32_t* gh = (uint32_t*)g_pt_hi;
                uint32_t* gl = (uint32_t*)g_pt_lo;
#pragma unroll
                for (int q=0;q<32;q++){
                    int idx = tid + q*256;          // 8192
                    int n = idx >> 6, u = idx & 63;
                    uint32_t hv = (uint32_t)ph[(2*u)*132 + n] | ((uint32_t)ph[(2*u+1)*132 + n] << 16);
                    uint32_t lv = (uint32_t)pl[(2*u)*132 + n] | ((uint32_t)pl[(2*u+1)*132 + n] << 16);
                    gh[(gb + n)*64 + u] = hv;
                    gl[(gb + n)*64 + u] = lv;
                }
            }
        } else if (ot == 1){
            float* ekS = (float*)(smem + EKR);
#pragma unroll
            for (int mt=0;mt<2;mt++)
#pragma unroll
                for (int ntl=0;ntl<8;ntl++)
#pragma unroll
                    for (int r=0;r<4;r++){
                        int o = wm*32 + mt*16 + g + ((r>>1)<<3);
                        int n = wn*64 + ntl*8 + tq*2 + (r&1);
                        ekS[o*EKSTR + n] = __expf(acc[mt][ntl][r]);
                    }
        } else {
            __syncthreads();
            float* vS = (float*)(smem + A_H);
#pragma unroll
            for (int mt=0;mt<2;mt++)
#pragma unroll
                for (int ntl=0;ntl<8;ntl++)
#pragma unroll
                    for (int r=0;r<4;r++){
                        int o = wm*32 + mt*16 + g + ((r>>1)<<3);
                        int n = wn*64 + ntl*8 + tq*2 + (r&1);
                        vS[o*EKSTR + n] = acc[mt][ntl][r];
                    }
            __syncthreads();

            // ---- fused ctx partials: warp = (head, e-half)
            const float* ekS = (const float*)(smem + EKR);
            const int h = wid >> 1, eh = wid & 1;
            const int dq = lane & 7, eq = lane >> 3;
            const float* ekp = ekS + (h*32 + dq*4)*EKSTR;
            const float* vp  = (const float*)(smem + A_H) + (h*32 + eh*16 + eq*4)*EKSTR;
            u64 c2[4][4];
            float kdv[4] = {0.f,0.f,0.f,0.f};
#pragma unroll
            for (int i=0;i<4;i++)
#pragma unroll
                for (int j=0;j<4;j++) c2[i][j] = 0ull;
            for (int n2=0;n2<64;n2++){
                float2 e2[4], v2[4];
#pragma unroll
                for (int i=0;i<4;i++) e2[i] = *(const float2*)(ekp + i*EKSTR + 2*n2);
#pragma unroll
                for (int j=0;j<4;j++) v2[j] = *(const float2*)(vp  + j*EKSTR + 2*n2);
                u64 ep[4], vv[4];
#pragma unroll
                for (int i=0;i<4;i++) ep[i] = pack2(e2[i].x, e2[i].y);
#pragma unroll
                for (int j=0;j<4;j++) vv[j] = pack2(v2[j].x, v2[j].y);
#pragma unroll
                for (int i=0;i<4;i++)
#pragma unroll
                    for (int j=0;j<4;j++) c2[i][j] = fma2(ep[i], vv[j], c2[i][j]);
                if (eq == 0 && eh == 0){
#pragma unroll
                    for (int i=0;i<4;i++) kdv[i] += e2[i].x + e2[i].y;
                }
            }
            const size_t pb = ((size_t)(b*NHh + h))*NSPLIT + nt;
            float* cp = g_cpart + pb*1024;
#pragma unroll
            for (int i=0;i<4;i++)
#pragma unroll
                for (int j=0;j<4;j++){
                    float2 t = unpack2(c2[i][j]);
                    cp[(dq*4+i)*32 + eh*16 + eq*4 + j] = t.x + t.y;
                }
            if (eq == 0 && eh == 0){
#pragma unroll
                for (int i=0;i<4;i++) g_kpart[pb*32 + dq*4 + i] = kdv[i];
            }
        }
    }
}

// ------------------------------ KB2: reduce ctx, fold w_out -> M2 bf16 hi/lo
__global__ void __launch_bounds__(256) kb2(const float* __restrict__ wout){
    const int h = blockIdx.x, b = blockIdx.y;
    __shared__ float sctx[32][33];
    __shared__ float kds[32];
    __shared__ float sW[128][33];
    const int tid = threadIdx.x;
    const size_t pbase = ((size_t)(b*NHh+h))*NSPLIT;

    if (tid < 32){
        float s = 0.f;
        for (int si=0; si<NSPLIT; si++) s += g_kpart[(pbase+si)*32 + tid];
        kds[tid] = s;
    }
#pragma unroll
    for (int q=0;q<16;q++){
        int idx = tid + q*256;
        int o = idx >> 5, e = idx & 31;
        sW[o][e] = wout[o*HID + h*32 + e];
    }
    __syncthreads();
    {
        float4 s = make_float4(0.f,0.f,0.f,0.f);
        for (int si=0; si<NSPLIT; si++){
            float4 p = *(const float4*)(g_cpart + (pbase+si)*1024 + tid*4);
            s.x+=p.x; s.y+=p.y; s.z+=p.z; s.w+=p.w;
        }
        int d = tid >> 3, e0 = (tid & 7)*4;
        float inv = 1.0f / kds[d];
        sctx[d][e0+0]=s.x*inv; sctx[d][e0+1]=s.y*inv;
        sctx[d][e0+2]=s.z*inv; sctx[d][e0+3]=s.w*inv;
    }
    __syncthreads();
    {
        int o = tid & 127, dh = (tid >> 7)*16;
        float m[16];
#pragma unroll
        for (int dd=0;dd<16;dd++) m[dd]=0.f;
        for (int e=0;e<32;e++){
            float wv = sW[o][e];
#pragma unroll
            for (int dd=0;dd<16;dd++) m[dd] += wv * sctx[dh+dd][e];
        }
#pragma unroll
        for (int dd=0;dd<16;dd++){
            __nv_bfloat16 hv = __float2bfloat16(m[dd]);
            size_t a = ((size_t)b*HID + o)*HID + h*32 + dh + dd;
            g_m_hi[a] = hv;
            g_m_lo[a] = __float2bfloat16(m[dd] - __bfloat162float(hv));
        }
    }
}

// ------------------------------ KC: HMMA out-proj, n-tile 64, 2 CTAs/SM
__global__ void __launch_bounds__(256, 2) kc(const float* __restrict__ bout,
                                             float* __restrict__ out){
    extern __shared__ char smem[];
    __shared__ float red1[8], red2[8];
    const int tid = threadIdx.x, wid = tid >> 5, lane = tid & 31;
    const int nt = blockIdx.x, b = blockIdx.y;
    const int wm = wid & 3, wn = wid >> 2;       // 4 M-warps x 2 N-warps (32 cols)
    const uint32_t sbase = smem_u32(smem);
    const int g = lane >> 2, tq = lane & 3;

    // stage A = M2 hi/lo [o][k], B = p tile hi/lo [n=64][k]
    {
        const uint4* mh = (const uint4*)g_m_hi + (size_t)b*2048;
        const uint4* ml = (const uint4*)g_m_lo + (size_t)b*2048;
        const uint4* ph = (const uint4*)g_pt_hi + ((size_t)b*NN + (size_t)nt*64)*16;
        const uint4* pl = (const uint4*)g_pt_lo + ((size_t)b*NN + (size_t)nt*64)*16;
        __nv_bfloat16* Ah = (__nv_bfloat16*)(smem + A_H);
        __nv_bfloat16* Al = (__nv_bfloat16*)(smem + A_L);
        __nv_bfloat16* Bh = (__nv_bfloat16*)(smem + KC_B_H);
        __nv_bfloat16* Bl = (__nv_bfloat16*)(smem + KC_B_L);
#pragma unroll
        for (int q=0;q<8;q++){
            int idx = tid + q*256;
            int r = idx >> 4, c8 = (idx & 15)*8;
            *(uint4*)(Ah + r*PADB + c8) = mh[idx];
            *(uint4*)(Al + r*PADB + c8) = ml[idx];
        }
#pragma unroll
        for (int q=0;q<4;q++){
            int idx = tid + q*256;                // 1024 uint4
            int r = idx >> 4, c8 = (idx & 15)*8;
            *(uint4*)(Bh + r*PADB + c8) = ph[idx];
            *(uint4*)(Bl + r*PADB + c8) = pl[idx];
        }
    }
    __syncthreads();

    float acc[2][4][4];
#pragma unroll
    for (int i=0;i<2;i++)
#pragma unroll
        for (int j=0;j<4;j++)
#pragma unroll
            for (int r=0;r<4;r++) acc[i][j][r] = 0.f;

    for (int k = 0; k < 128; k += 16){
        uint32_t ah[2][4], al[2][4];
#pragma unroll
        for (int mt=0;mt<2;mt++){
            int row = wm*32 + mt*16 + (lane & 15);
            int kh  = k + ((lane >> 4) << 3);
            ldsm4(ah[mt], sbase + A_H + (uint32_t)(row*PADB + kh)*2);
            ldsm4(al[mt], sbase + A_L + (uint32_t)(row*PADB + kh)*2);
        }
        uint32_t bh[4][2], bl[4][2];
#pragma unroll
        for (int p=0;p<2;p++){
            int nr = wn*32 + p*16 + ((lane >> 4) << 3) + (lane & 7);
            int kh = k + (((lane >> 3) & 1) << 3);
            uint32_t r4[4];
            ldsm4(r4, sbase + KC_B_H + (uint32_t)(nr*PADB + kh)*2);
            bh[2*p][0]=r4[0]; bh[2*p][1]=r4[1]; bh[2*p+1][0]=r4[2]; bh[2*p+1][1]=r4[3];
            ldsm4(r4, sbase + KC_B_L + (uint32_t)(nr*PADB + kh)*2);
            bl[2*p][0]=r4[0]; bl[2*p][1]=r4[1]; bl[2*p+1][0]=r4[2]; bl[2*p+1][1]=r4[3];
        }
#pragma unroll
        for (int mt=0;mt<2;mt++)
#pragma unroll
            for (int ntl=0;ntl<4;ntl++) mma_bf16(acc[mt][ntl], ah[mt], bh[ntl]);
#pragma unroll
        for (int mt=0;mt<2;mt++)
#pragma unroll
            for (int ntl=0;ntl<4;ntl++) mma_bf16(acc[mt][ntl], ah[mt], bl[ntl]);
#pragma unroll
        for (int mt=0;mt<2;mt++)
#pragma unroll
            for (int ntl=0;ntl<4;ntl++) mma_bf16(acc[mt][ntl], al[mt], bh[ntl]);
    }

    // epilogue: bias, writes, GN partials
    float bias[4];
#pragma unroll
    for (int r2=0;r2<4;r2++) bias[r2] = bout[wm*32 + r2*8 + g];
    float s1 = 0.f, s2 = 0.f;
#pragma unroll
    for (int mt=0;mt<2;mt++)
#pragma unroll
        for (int ntl=0;ntl<4;ntl++){
#pragma unroll
            for (int half=0; half<2; half++){
                float bv = bias[mt*2 + half];
                float v0 = acc[mt][ntl][half*2+0] + bv;
                float v1 = acc[mt][ntl][half*2+1] + bv;
                s1 += v0 + v1;
                s2 += v0*v0 + v1*v1;
                int row = wm*32 + mt*16 + half*8 + g;
                int col = nt*64 + wn*32 + ntl*8 + tq*2;
                *(float2*)(out + ((size_t)(b*HID + row))*NN + col) = make_float2(v0, v1);
            }
        }
#pragma unroll
    for (int m=1;m<32;m<<=1){
        s1 += __shfl_xor_sync(0xffffffffu, s1, m);
        s2 += __shfl_xor_sync(0xffffffffu, s2, m);
    }
    if (lane == 0){ red1[wid] = s1; red2[wid] = s2; }
    __syncthreads();
    if (tid == 0){
        float a=0.f, c2s=0.f;
#pragma unroll
        for (int w=0; w<8; w++){ a += red1[w]; c2s += red2[w]; }
        g_part[(b*64+nt)*2 + 0] = a;
        g_part[(b*64+nt)*2 + 1] = c2s;
    }
}

// ------------------------------ KD: GroupNorm finalize
__global__ void __launch_bounds__(256) kd(float* __restrict__ out,
                                          const float* __restrict__ gamma,
                                          const float* __restrict__ beta){
    const int cx = blockIdx.x, b = blockIdx.y;
    __shared__ float sm[2];
    const int tid = threadIdx.x;
    if (tid == 0){
        float s=0.f, s2=0.f;
#pragma unroll
        for (int i=0;i<64;i++){
            s  += g_part[(b*64+i)*2 + 0];
            s2 += g_part[(b*64+i)*2 + 1];
        }
        sm[0]=s; sm[1]=s2;
    }
    __syncthreads();
    const float invN = 1.0f / ((float)HID * (float)NN);
    float mean = sm[0]*invN;
    float var  = sm[1]*invN - mean*mean;
    float rstd = rsqrtf(var + 1e-5f);

    float* base = out + (size_t)b*HID*NN + (size_t)cx*16384;
#pragma unroll
    for (int q=0;q<16;q++){
        int fi = tid + q*256;
        int c  = (cx*16384 + fi*4) >> 12;
        float a  = gamma[c]*rstd;
        float bb = beta[c] - mean*a;
        float4 v = *(float4*)(base + fi*4);
        v.x = v.x*a + bb; v.y = v.y*a + bb;
        v.z = v.z*a + bb; v.w = v.w*a + bb;
        *(float4*)(base + fi*4) = v;
    }
}

// ---------------------------------------------------------------------------
extern "C" void kernel_launch(void* const* d_in, const int* in_sizes, int n_in,
                              void* d_out, int out_size){
    (void)in_sizes; (void)n_in; (void)out_size;
    const float* x     = (const float*)d_in[0];
    const float* wqkv  = (const float*)d_in[1];
    const float* wout  = (const float*)d_in[2];
    const float* bout  = (const float*)d_in[3];
    const float* gamma = (const float*)d_in[4];
    const float* beta  = (const float*)d_in[5];
    float* out = (float*)d_out;

    cudaFuncSetAttribute(ka, cudaFuncAttributeMaxDynamicSharedMemorySize, KA_SMEM);
    cudaFuncSetAttribute(kc, cudaFuncAttributeMaxDynamicSharedMemorySize, KC_SMEM);

    prep_w<<<192, 256>>>(wqkv);
    ka <<<dim3(32,32), 256, KA_SMEM>>>(x);
    kb2<<<dim3(4,32),  256>>>(wout);
    kc <<<dim3(64,32), 256, KC_SMEM>>>(bout, out);
    kd <<<dim3(32,32), 256>>>(out, gamma, beta);
}